// round 4
// baseline (speedup 1.0000x reference)
#include <cuda_runtime.h>
#include <math.h>

#define NUM_TOKENS 16384
#define D_MODEL    2048
#define NUM_EXP    8
#define D4         (D_MODEL / 4)        // 512 float4 per row

#define NUM_CTAS     128
#define THREADS      512
#define WARPS        16
#define TOK_PER_CTA  128
#define TOK_PER_HALF 64
#define TOK_PER_WARP 4                  // per half
#define CHUNK_K4     32                 // float4 per row per chunk (128 floats)
#define KCHUNKS      16                 // 2048 / 128
#define TOTAL_CHUNKS (2 * KCHUNKS)      // 2 halves x 16
#define NBUF         3
#define CHUNK_F4     (TOK_PER_HALF * CHUNK_K4)   // 2048 float4 = 32KB

// Packed fp32x2 FMA (Blackwell): d = a*b + d, two fp32 lanes per instruction.
__device__ __forceinline__ void fma2(unsigned long long& d,
                                     unsigned long long a,
                                     unsigned long long b)
{
    asm("fma.rn.f32x2 %0, %1, %2, %0;" : "+l"(d) : "l"(a), "l"(b));
}

__device__ __forceinline__ float fold2(unsigned long long v)
{
    float lo, hi;
    asm("mov.b64 {%0, %1}, %2;" : "=f"(lo), "=f"(hi) : "l"(v));
    return lo + hi;
}

__device__ __forceinline__ void cp_async16(void* smem_dst, const void* gmem_src)
{
    unsigned s = (unsigned)__cvta_generic_to_shared(smem_dst);
    asm volatile("cp.async.cg.shared.global [%0], [%1], 16;\n"
                 :: "r"(s), "l"(gmem_src));
}

extern __shared__ float sm[];
// layout: sW [8*2048 floats = 64KB] | xbuf[3][2048 float4 = 32KB each]

__global__ __launch_bounds__(THREADS, 1)
void gate_kernel(const float* __restrict__ x,
                 const float* __restrict__ W,
                 float* __restrict__ out,
                 int write_experts)
{
    float4* sW4 = reinterpret_cast<float4*>(sm);
    float4* xbuf = reinterpret_cast<float4*>(sm + NUM_EXP * D_MODEL);

    const int tid  = threadIdx.x;
    const int warp = tid >> 5;
    const int lane = tid & 31;
    const int tok0 = blockIdx.x * TOK_PER_CTA;

    // --- Stage W into shared memory (64 KB) ---
    {
        const float4* W4 = reinterpret_cast<const float4*>(W);
        #pragma unroll
        for (int i = tid; i < NUM_EXP * D4; i += THREADS)
            sW4[i] = W4[i];
    }

    const float4* x4 = reinterpret_cast<const float4*>(x);

    // Staging lambda: chunk cc (0..31) -> buffer b. 512 threads x 4 cp.async.
    // chunk cc: half h = cc>>4, K-chunk c = cc&15.
    // row r (0..63) = local token; global float4 = x4[(tok)*512 + c*32 + j]
    auto stage = [&](int cc, int b) {
        const int h = cc >> 4;
        const int c = cc & 15;
        const int j  = tid & 31;        // float4 column within chunk row
        const int r0 = tid >> 5;        // rows r0, r0+16, r0+32, r0+48
        float4* dst = xbuf + b * CHUNK_F4;
        const float4* src = x4 + (size_t)(tok0 + h * TOK_PER_HALF) * D4 + c * 32 + j;
        #pragma unroll
        for (int k = 0; k < 4; k++) {
            int r = r0 + k * 16;
            cp_async16(dst + r * 32 + j, src + (size_t)r * D4);
        }
    };

    __syncthreads();   // sW visible (plain stores) before anyone computes

    // Prologue: prefetch chunks 0,1,2
    stage(0, 0); asm volatile("cp.async.commit_group;\n" ::: "memory");
    stage(1, 1); asm volatile("cp.async.commit_group;\n" ::: "memory");
    stage(2, 2); asm volatile("cp.async.commit_group;\n" ::: "memory");

    unsigned long long acc[NUM_EXP][TOK_PER_WARP];

    const ulonglong2* wq = reinterpret_cast<const ulonglong2*>(sm);

    for (int cc = 0; cc < TOTAL_CHUNKS; cc++) {
        const int h = cc >> 4;
        const int c = cc & 15;
        const int b = cc % NBUF;

        if (c == 0) {
            #pragma unroll
            for (int e = 0; e < NUM_EXP; e++)
                #pragma unroll
                for (int t = 0; t < TOK_PER_WARP; t++)
                    acc[e][t] = 0ull;
        }

        // Wait for chunk cc (keep at most the 2 most recent groups pending)
        asm volatile("cp.async.wait_group 2;\n" ::: "memory");
        __syncthreads();

        // --- Compute chunk: warp owns rows [warp*4, warp*4+4) of the 64 ---
        {
            const ulonglong2* xq =
                reinterpret_cast<const ulonglong2*>(xbuf + b * CHUNK_F4);
            ulonglong2 xr[TOK_PER_WARP];
            #pragma unroll
            for (int t = 0; t < TOK_PER_WARP; t++)
                xr[t] = xq[(warp * TOK_PER_WARP + t) * 32 + lane];

            #pragma unroll
            for (int e = 0; e < NUM_EXP; e++) {
                ulonglong2 wv = wq[e * D4 + c * 32 + lane];
                #pragma unroll
                for (int t = 0; t < TOK_PER_WARP; t++) {
                    fma2(acc[e][t], xr[t].x, wv.x);
                    fma2(acc[e][t], xr[t].y, wv.y);
                }
            }
        }
        __syncthreads();   // all warps done reading buffer b

        // Refill freed buffer with chunk cc+3 (uniform commit keeps counts aligned)
        if (cc + 3 < TOTAL_CHUNKS) stage(cc + 3, b);
        asm volatile("cp.async.commit_group;\n" ::: "memory");

        // --- Half epilogue: finalize 4 tokens per warp ---
        if (c == KCHUNKS - 1) {
            float s[NUM_EXP][TOK_PER_WARP];
            #pragma unroll
            for (int e = 0; e < NUM_EXP; e++)
                #pragma unroll
                for (int t = 0; t < TOK_PER_WARP; t++)
                    s[e][t] = fold2(acc[e][t]);

            #pragma unroll
            for (int off = 16; off >= 1; off >>= 1)
                #pragma unroll
                for (int e = 0; e < NUM_EXP; e++)
                    #pragma unroll
                    for (int t = 0; t < TOK_PER_WARP; t++)
                        s[e][t] += __shfl_xor_sync(0xFFFFFFFFu, s[e][t], off);

            float logit[NUM_EXP];
            #pragma unroll
            for (int e = 0; e < NUM_EXP; e++) {
                float v = s[e][0];
                #pragma unroll
                for (int t = 1; t < TOK_PER_WARP; t++)
                    v = (lane == t) ? s[e][t] : v;
                logit[e] = v;
            }

            if (lane < TOK_PER_WARP) {
                const int tok = tok0 + h * TOK_PER_HALF + warp * TOK_PER_WARP + lane;

                // top-2 scan; strict '>' keeps lowest index on ties (JAX top_k)
                float v1 = logit[0], v2 = -INFINITY;
                int   i1 = 0,        i2 = 0;
                #pragma unroll
                for (int e = 1; e < NUM_EXP; e++) {
                    float le = logit[e];
                    if (le > v1)      { v2 = v1; i2 = i1; v1 = le; i1 = e; }
                    else if (le > v2) { v2 = le; i2 = e; }
                }

                // softmax + top-2 + renorm == 2-way softmax over top-2 logits
                float r  = __expf(v2 - v1);
                float w1 = 1.0f / (1.0f + r);
                float w2 = 1.0f - w1;

                out[tok * 2 + 0] = w1;
                out[tok * 2 + 1] = w2;
                if (write_experts) {
                    out[2 * NUM_TOKENS + tok * 2 + 0] = (float)i1;
                    out[2 * NUM_TOKENS + tok * 2 + 1] = (float)i2;
                }
            }
        }
    }
}

extern "C" void kernel_launch(void* const* d_in, const int* in_sizes, int n_in,
                              void* d_out, int out_size)
{
    const float* x = (const float*)d_in[0];
    const float* W = (const float*)d_in[1];
    float* out = (float*)d_out;

    int write_experts = (out_size >= 4 * NUM_TOKENS) ? 1 : 0;

    const int smem = NUM_EXP * D_MODEL * (int)sizeof(float)     // 64 KB W
                   + NBUF * CHUNK_F4 * (int)sizeof(float4);     // 96 KB x buffers
    cudaFuncSetAttribute(gate_kernel, cudaFuncAttributeMaxDynamicSharedMemorySize, smem);

    gate_kernel<<<NUM_CTAS, THREADS, smem>>>(x, W, out, write_experts);
}